// round 8
// baseline (speedup 1.0000x reference)
#include <cuda_runtime.h>
#include <cuda_bf16.h>

// Fixed problem shape
#define B_    4
#define N_    64
#define HW_   512
#define TH_   128    // tile rows (h)
#define TW_   64     // tile cols (w)
#define MAXC  16     // labels per chunk

// One-wave latency-optimized sparse fused kernel:
//  - 128 blocks (<=148 SMs, single wave), 512 threads
//  - warp 0: compaction + normalization (analytic sigma*sqrt(2pi) unless
//    border-clipped); warps 1-15 build windowed gaussians concurrently
//  - 2 __syncthreads on the common path
__global__ __launch_bounds__(512) void density_sparse4(
    const float* __restrict__ labels,   // (B, N, 2)
    const float* __restrict__ sigma_p,  // scalar
    float* __restrict__ out)            // (B, 1, 512, 512)
{
    __shared__ __align__(16) float s_gy[MAXC][TH_];   // raw gy (8 KB)
    __shared__ __align__(16) float s_gx[MAXC][TW_];   // raw gx (4 KB)
    __shared__ __align__(16) float s_lab[N_ * 2];
    __shared__ float s_inv[MAXC];                     // 1/(sum_x*sum_y)
    __shared__ int   s_list[N_];
    __shared__ int   s_cnt;

    const int b  = blockIdx.z;
    const int h0 = blockIdx.y * TH_;
    const int w0 = blockIdx.x * TW_;
    const int t  = threadIdx.x;                 // 0..511
    const int lane = t & 31;

    const float sigma  = sigma_p[0];
    const float inv2   = 1.0f / (2.0f * sigma * sigma);
    const float R      = 6.5f * sigma;          // e^{-21} truncation
    const float s_an   = sigma * 2.5066282746310002f;   // sigma*sqrt(2*pi)

    // stage labels to smem (used by exp + norm phases)
    if (t < N_ * 2) s_lab[t] = __ldg(&labels[b * N_ * 2 + t]);

    // warp 0: compaction. Each lane tests labels lane and lane+32.
    if (t < 32) {
        const float2* lab2 = (const float2*)labels + b * N_;
        float2 p0 = __ldg(&lab2[lane]);
        float2 p1 = __ldg(&lab2[lane + 32]);
        const float wlo = (float)w0 - R, whi = (float)(w0 + TW_ - 1) + R;
        const float hlo = (float)h0 - R, hhi = (float)(h0 + TH_ - 1) + R;
        bool a0 = (p0.x >= wlo) && (p0.x <= whi) && (p0.y >= hlo) && (p0.y <= hhi);
        bool a1 = (p1.x >= wlo) && (p1.x <= whi) && (p1.y >= hlo) && (p1.y <= hhi);
        unsigned m0 = __ballot_sync(0xFFFFFFFFu, a0);
        unsigned m1 = __ballot_sync(0xFFFFFFFFu, a1);
        unsigned below = (1u << lane) - 1u;
        if (a0) s_list[__popc(m0 & below)] = lane;
        if (a1) s_list[__popc(m0) + __popc(m1 & below)] = lane + 32;
        if (lane == 0) s_cnt = __popc(m0) + __popc(m1);
    }
    __syncthreads();                               // BAR #1
    const int cnt = s_cnt;

    float acc[4][4];
    #pragma unroll
    for (int i = 0; i < 4; i++)
        #pragma unroll
        for (int j = 0; j < 4; j++) acc[i][j] = 0.0f;

    const int tx = t & 15;      // 4 cols each  (0..15)
    const int ty = t >> 4;      // 4 rows each  (0..31)

    for (int c0 = 0; c0 < cnt; c0 += MAXC) {
        const int nc = min(MAXC, cnt - c0);

        if (t < 32) {
            // ---- warp 0: normalization, lane-per-(label,axis) --------------
            const int li   = lane >> 1;            // 0..15
            const int axis = lane & 1;             // 0 = x, 1 = y
            float s = s_an;
            float l = 0.0f;
            if (li < nc) l = s_lab[2 * s_list[c0 + li] + axis];
            if (li < nc && (l < R || l > 511.0f - R)) {
                // border-clipped: 4-way ILP partial sums over the window
                int lo = (int)ceilf(l - R);  if (lo < 0) lo = 0;
                int hi = (int)floorf(l + R); if (hi > HW_ - 1) hi = HW_ - 1;
                float p0 = 0.f, p1 = 0.f, p2 = 0.f, p3 = 0.f;
                int i = lo;
                for (; i + 3 <= hi; i += 4) {
                    float d0 = (float)i     - l;
                    float d1 = (float)(i+1) - l;
                    float d2 = (float)(i+2) - l;
                    float d3 = (float)(i+3) - l;
                    p0 += __expf(-d0 * d0 * inv2);
                    p1 += __expf(-d1 * d1 * inv2);
                    p2 += __expf(-d2 * d2 * inv2);
                    p3 += __expf(-d3 * d3 * inv2);
                }
                for (; i <= hi; i++) {
                    float d = (float)i - l;
                    p0 += __expf(-d * d * inv2);
                }
                s = (p0 + p1) + (p2 + p3);
            }
            float so = __shfl_xor_sync(0xFFFFFFFFu, s, 1);
            if (li < nc && axis == 0) s_inv[li] = 1.0f / (s * so);
        } else {
            // ---- warps 1-15: raw windowed gaussians (unscaled) -------------
            // nc * 192 values over 480 threads
            for (int idx = t - 32; idx < nc * (TH_ + TW_); idx += 480) {
                const int li = idx / (TH_ + TW_);
                const int r  = idx - li * (TH_ + TW_);
                const int n  = s_list[c0 + li];
                if (r < TH_) {
                    float l = s_lab[2 * n + 1];
                    float d = (float)(h0 + r) - l;
                    s_gy[li][r] = (fabsf(d) <= R) ? __expf(-d * d * inv2) : 0.0f;
                } else {
                    float l = s_lab[2 * n];
                    float d = (float)(w0 + (r - TH_)) - l;
                    s_gx[li][r - TH_] = (fabsf(d) <= R) ? __expf(-d * d * inv2) : 0.0f;
                }
            }
        }
        __syncthreads();                           // BAR #2

        // ---- rank-nc outer-product accumulation (inv folded into a) --------
        #pragma unroll 4
        for (int li = 0; li < nc; li++) {
            const float inv = s_inv[li];
            float4 a  = *reinterpret_cast<const float4*>(&s_gy[li][ty * 4]);
            float4 bx = *reinterpret_cast<const float4*>(&s_gx[li][tx * 4]);
            a.x *= inv; a.y *= inv; a.z *= inv; a.w *= inv;
            acc[0][0] += a.x * bx.x; acc[0][1] += a.x * bx.y; acc[0][2] += a.x * bx.z; acc[0][3] += a.x * bx.w;
            acc[1][0] += a.y * bx.x; acc[1][1] += a.y * bx.y; acc[1][2] += a.y * bx.z; acc[1][3] += a.y * bx.w;
            acc[2][0] += a.z * bx.x; acc[2][1] += a.z * bx.y; acc[2][2] += a.z * bx.z; acc[2][3] += a.z * bx.w;
            acc[3][0] += a.w * bx.x; acc[3][1] += a.w * bx.y; acc[3][2] += a.w * bx.z; acc[3][3] += a.w * bx.w;
        }
        if (c0 + MAXC < cnt) __syncthreads();      // only if another chunk
    }

    // ---- store (zeros where no label overlaps) ------------------------------
    float* ob = out + ((size_t)b * HW_ + h0 + ty * 4) * HW_ + w0 + tx * 4;
    #pragma unroll
    for (int i = 0; i < 4; i++) {
        float4 r = make_float4(acc[i][0], acc[i][1], acc[i][2], acc[i][3]);
        *reinterpret_cast<float4*>(&ob[i * (size_t)HW_]) = r;
    }
}

extern "C" void kernel_launch(void* const* d_in, const int* in_sizes, int n_in,
                              void* d_out, int out_size) {
    // d_in[0]: batch_images (unused, shape only)
    // d_in[1]: batch_labels (4,64,2) f32
    // d_in[2]: sigma scalar f32
    const float* labels = (const float*)d_in[1];
    const float* sigma  = (const float*)d_in[2];
    float* out = (float*)d_out;

    dim3 grid(HW_ / TW_, HW_ / TH_, B_);   // (8, 4, 4) = 128 blocks, one wave
    density_sparse4<<<grid, 512>>>(labels, sigma, out);
}

// round 9
// speedup vs baseline: 1.2108x; 1.2108x over previous
#include <cuda_runtime.h>
#include <cuda_bf16.h>

// Fixed problem shape
#define B_    4
#define N_    64
#define HW_   512
#define T_    64     // tile 64x64
#define MAXC  8      // labels per chunk (== #warps)

__device__ __forceinline__ float ex2(float x) {
    float r;
    asm("ex2.approx.f32 %0, %1;" : "=f"(r) : "f"(x));
    return r;
}

// Sparse fused kernel (round-5 structure + shortened chain):
//  - 256 blocks x 256 threads (2 blocks/SM overlap)
//  - warp 0 compacts labels directly into float2 smem (no indirection)
//  - values phase over all threads; norm per-warp in same region; 1 bar/chunk
//  - analytic normalization sigma*sqrt(2pi) unless border-clipped
//  - raw ex2.approx, no window clamp in values phase
__global__ __launch_bounds__(256) void density_sparse5(
    const float* __restrict__ labels,   // (B, N, 2)
    const float* __restrict__ sigma_p,  // scalar
    float* __restrict__ out)            // (B, 1, 512, 512)
{
    __shared__ __align__(16) float  s_gy[MAXC][T_];   // raw gy (2 KB)
    __shared__ __align__(16) float  s_gx[MAXC][T_];   // raw gx (2 KB)
    __shared__ __align__(16) float2 s_clab[N_];       // compacted labels
    __shared__ float s_inv[MAXC];                     // 1/(sum_x*sum_y)
    __shared__ int   s_cnt;

    const int b  = blockIdx.z;
    const int h0 = blockIdx.y * T_;
    const int w0 = blockIdx.x * T_;
    const int t  = threadIdx.x;                 // 0..255
    const int lane = t & 31;

    const float sigma = sigma_p[0];
    const float inv2  = 1.0f / (2.0f * sigma * sigma);
    const float cexp  = -inv2 * 1.4426950408889634f;  // fold log2(e)
    const float R     = 6.5f * sigma;                 // e^{-21} truncation
    const float s_an  = sigma * 2.5066282746310002f;  // sigma*sqrt(2*pi)

    // warp 0: compaction -> compacted float2 labels + count
    if (t < 32) {
        const float2* lab2 = (const float2*)labels + b * N_;
        float2 p0 = __ldg(&lab2[lane]);
        float2 p1 = __ldg(&lab2[lane + 32]);
        const float wlo = (float)w0 - R, whi = (float)(w0 + T_ - 1) + R;
        const float hlo = (float)h0 - R, hhi = (float)(h0 + T_ - 1) + R;
        bool a0 = (p0.x >= wlo) && (p0.x <= whi) && (p0.y >= hlo) && (p0.y <= hhi);
        bool a1 = (p1.x >= wlo) && (p1.x <= whi) && (p1.y >= hlo) && (p1.y <= hhi);
        unsigned m0 = __ballot_sync(0xFFFFFFFFu, a0);
        unsigned m1 = __ballot_sync(0xFFFFFFFFu, a1);
        unsigned below = (1u << lane) - 1u;
        if (a0) s_clab[__popc(m0 & below)] = p0;
        if (a1) s_clab[__popc(m0) + __popc(m1 & below)] = p1;
        if (lane == 0) s_cnt = __popc(m0) + __popc(m1);
    }
    __syncthreads();                               // BAR #1
    const int cnt = s_cnt;

    float acc[4][4];
    #pragma unroll
    for (int i = 0; i < 4; i++)
        #pragma unroll
        for (int j = 0; j < 4; j++) acc[i][j] = 0.0f;

    const int tx = t & 15;      // 4 cols each (0..15)
    const int ty = t >> 4;      // 4 rows each (0..15)
    const int wi = t >> 5;      // warp id 0..7

    for (int c0 = 0; c0 < cnt; c0 += MAXC) {
        const int nc = min(MAXC, cnt - c0);

        // ---- values: nc*128 elems over 256 threads (no window clamp:
        //      ex2 underflows to 0 beyond ~53px, matching the reference) ----
        for (int idx = t; idx < (nc << 7); idx += 256) {
            const int li = idx >> 7;
            const int r  = idx & 127;
            const float2 L = s_clab[c0 + li];
            if (r < T_) {
                float d = (float)(h0 + r) - L.y;
                s_gy[li][r] = ex2(d * d * cexp);
            } else {
                float d = (float)(w0 + (r - T_)) - L.x;
                s_gx[li][r - T_] = ex2(d * d * cexp);
            }
        }

        // ---- normalization: warp wi handles chunk label wi -----------------
        if (wi < nc) {
            const float2 L = s_clab[c0 + wi];
            const bool clipped = (L.x < R) || (L.x > 511.0f - R) ||
                                 (L.y < R) || (L.y > 511.0f - R);
            if (!clipped) {
                if (lane == 0) s_inv[wi] = 1.0f / (s_an * s_an);
            } else {
                // lanes 0-15: x axis, lanes 16-31: y axis
                const int axis = lane >> 4;
                const int j    = lane & 15;
                const float l  = axis ? L.y : L.x;
                float s;
                if (l >= R && l <= 511.0f - R) {
                    s = (j == 0) ? s_an : 0.0f;
                } else {
                    int lo = (int)ceilf(l - R);  if (lo < 0) lo = 0;
                    int hi = (int)floorf(l + R); if (hi > HW_ - 1) hi = HW_ - 1;
                    s = 0.0f;
                    for (int i = lo + j; i <= hi; i += 16) {
                        float d = (float)i - l;
                        s += ex2(d * d * cexp);
                    }
                }
                s += __shfl_xor_sync(0xFFFFFFFFu, s, 1);
                s += __shfl_xor_sync(0xFFFFFFFFu, s, 2);
                s += __shfl_xor_sync(0xFFFFFFFFu, s, 4);
                s += __shfl_xor_sync(0xFFFFFFFFu, s, 8);
                float so = __shfl_xor_sync(0xFFFFFFFFu, s, 16);
                if (lane == 0) s_inv[wi] = 1.0f / (s * so);
            }
        }
        __syncthreads();                           // BAR #2

        // ---- rank-nc outer-product accumulation (inv folded into a) --------
        #pragma unroll 4
        for (int li = 0; li < nc; li++) {
            const float inv = s_inv[li];
            float4 a  = *reinterpret_cast<const float4*>(&s_gy[li][ty * 4]);
            float4 bx = *reinterpret_cast<const float4*>(&s_gx[li][tx * 4]);
            a.x *= inv; a.y *= inv; a.z *= inv; a.w *= inv;
            acc[0][0] += a.x * bx.x; acc[0][1] += a.x * bx.y; acc[0][2] += a.x * bx.z; acc[0][3] += a.x * bx.w;
            acc[1][0] += a.y * bx.x; acc[1][1] += a.y * bx.y; acc[1][2] += a.y * bx.z; acc[1][3] += a.y * bx.w;
            acc[2][0] += a.z * bx.x; acc[2][1] += a.z * bx.y; acc[2][2] += a.z * bx.z; acc[2][3] += a.z * bx.w;
            acc[3][0] += a.w * bx.x; acc[3][1] += a.w * bx.y; acc[3][2] += a.w * bx.z; acc[3][3] += a.w * bx.w;
        }
        if (c0 + MAXC < cnt) __syncthreads();      // only if another chunk
    }

    // ---- store (zeros where no label overlaps) ------------------------------
    float* ob = out + ((size_t)b * HW_ + h0 + ty * 4) * HW_ + w0 + tx * 4;
    #pragma unroll
    for (int i = 0; i < 4; i++) {
        float4 r = make_float4(acc[i][0], acc[i][1], acc[i][2], acc[i][3]);
        *reinterpret_cast<float4*>(&ob[i * (size_t)HW_]) = r;
    }
}

extern "C" void kernel_launch(void* const* d_in, const int* in_sizes, int n_in,
                              void* d_out, int out_size) {
    // d_in[0]: batch_images (unused, shape only)
    // d_in[1]: batch_labels (4,64,2) f32
    // d_in[2]: sigma scalar f32
    const float* labels = (const float*)d_in[1];
    const float* sigma  = (const float*)d_in[2];
    float* out = (float*)d_out;

    dim3 grid(HW_ / T_, HW_ / T_, B_);   // (8, 8, 4) = 256 blocks
    density_sparse5<<<grid, 256>>>(labels, sigma, out);
}